// round 14
// baseline (speedup 1.0000x reference)
#include <cuda_runtime.h>

#define NMAX 100000
#define EMAX 3200000
#define CIN 128
#define HID 64
#define CAP 128   // max tracked degree (Poisson(32): P(deg>128) ~ 1e-40)

// ---------------- device scratch (no allocations allowed) ----------------
__device__ int   g_cnt[NMAX];     // slot counter during build == final degree
__device__ int   g_is64;
__device__ int   g_ell[(size_t)NMAX * CAP];
__device__ float g_h[(size_t)NMAX * HID];
__device__ float g_a[(size_t)NMAX * HID];

__device__ __forceinline__ int load_idx(const void* ei, size_t pos, int is64) {
    return is64 ? (int)((const long long*)ei)[pos] : ((const int*)ei)[pos];
}

// ---------------- launch 0: zero counters + parallel dtype detect ----------
__global__ void k_setup(const unsigned int* __restrict__ ew, int N) {
    int i = blockIdx.x * blockDim.x + threadIdx.x;
    if (i < N) g_cnt[i] = 0;
    if (blockIdx.x == 0) {
        __shared__ int bad;
        if (threadIdx.x == 0) bad = 0;
        __syncthreads();
        // int64 edge values < 2^32 have zero high 32-bit words; int32 data won't.
        if (threadIdx.x < 64 && ew[2 * threadIdx.x + 1] != 0u) atomicExch(&bad, 1);
        __syncthreads();
        if (threadIdx.x == 0) g_is64 = bad ? 0 : 1;
    }
}

// ---------------- launch 1: ELL adjacency build (slot counter == degree) ----
__global__ void k_build(const void* __restrict__ ei, int E, int N) {
    int e = blockIdx.x * blockDim.x + threadIdx.x;
    if (e < E) {
        int is64 = g_is64;
        int d = load_idx(ei, (size_t)E + e, is64);
        if ((unsigned)d < (unsigned)N) {
            int s = load_idx(ei, e, is64);
            if ((unsigned)s >= (unsigned)N) s = d;
            int p = atomicAdd(&g_cnt[d], 1);
            if (p < CAP) g_ell[(size_t)d * CAP + p] = s;
        }
    }
}

// ---------------- GEMM body: H[row,:] = (X[row,:] @ W) * rsqrt(cnt[row]+1) ----
template <int CINT, int COUT>
__device__ __forceinline__ void gemm_rows(const float* __restrict__ X,
                                          const float* __restrict__ W,
                                          float* __restrict__ H, int N,
                                          int rowBlock) {
    __shared__ float4 sW[CINT * COUT / 4];
    for (int i = threadIdx.x; i < CINT * COUT / 4; i += blockDim.x)
        sW[i] = ((const float4*)W)[i];
    __syncthreads();

    int row = rowBlock * blockDim.x + threadIdx.x;
    if (row >= N) return;

    float acc[COUT];
#pragma unroll
    for (int j = 0; j < COUT; j++) acc[j] = 0.f;

    const float4* x4 = (const float4*)(X + (size_t)row * CINT);
#pragma unroll 2
    for (int k4 = 0; k4 < CINT / 4; k4++) {
        float4 xv = x4[k4];
        int k = k4 * 4;
#pragma unroll
        for (int kk = 0; kk < 4; kk++) {
            float xs = (kk == 0) ? xv.x : (kk == 1) ? xv.y : (kk == 2) ? xv.z : xv.w;
            const float4* wr = &sW[(k + kk) * (COUT / 4)];
#pragma unroll
            for (int j4 = 0; j4 < COUT / 4; j4++) {
                float4 w = wr[j4];
                acc[4 * j4 + 0] += xs * w.x;
                acc[4 * j4 + 1] += xs * w.y;
                acc[4 * j4 + 2] += xs * w.z;
                acc[4 * j4 + 3] += xs * w.w;
            }
        }
    }
    float sc = rsqrtf((float)(g_cnt[row] + 1));  // dinv folding (+1 self loop)
    float4* hr = (float4*)(H + (size_t)row * COUT);
#pragma unroll
    for (int j = 0; j < COUT / 4; j++)
        hr[j] = make_float4(acc[4 * j] * sc, acc[4 * j + 1] * sc,
                            acc[4 * j + 2] * sc, acc[4 * j + 3] * sc);
}

__global__ void __launch_bounds__(128) k_gemm1(const float* __restrict__ X,
                                               const float* __restrict__ W1,
                                               float* __restrict__ H, int N) {
    gemm_rows<CIN, HID>(X, W1, H, N, blockIdx.x);
}

__global__ void __launch_bounds__(128) k_gemm2(const float* __restrict__ A,
                                               const float* __restrict__ W2,
                                               float* __restrict__ H, int N) {
    gemm_rows<HID, HID>(A, W2, H, N, blockIdx.x);
}

// ---------------- launches 3/5: ELL gather-aggregate (float4, 2 rows/warp-op) --
// One warp per dst. lane = (pair, q): pair = lane>>4 selects one of 2 edges
// per step, q = lane&15 selects the float4 (4 channels) within the 64-ch row.
// Each warp LDG.128 fetches TWO 256B feature rows. 8 batched iterations keep
// 16 rows in flight. Halves combined via shfl_xor(16); half-warp stores.
template <bool RELU>
__global__ void __launch_bounds__(256) k_agg(const float* __restrict__ H,
                                             const float* __restrict__ bias,
                                             float* __restrict__ O, int N) {
    int warp = (blockIdx.x * blockDim.x + threadIdx.x) >> 5;
    int lane = threadIdx.x & 31;
    if (warp >= N) return;
    int dst = warp;
    int pair = lane >> 4;
    int q = lane & 15;

    int cnt = g_cnt[dst];
    int deg = cnt < CAP ? cnt : CAP;
    const int* __restrict__ ell = g_ell + (size_t)dst * CAP;
    const float4* __restrict__ H4 = (const float4*)H;

    float4 acc = make_float4(0.f, 0.f, 0.f, 0.f);

    for (int j0 = 0; j0 < deg; j0 += 32) {
        int m = deg - j0;
        if (m > 32) m = 32;
        int idx = (lane < m) ? ell[j0 + lane] : 0;  // one coalesced LDG: 32 ids

        int k = 0;
        for (; k + 16 <= m; k += 16) {
            int s0 = __shfl_sync(0xFFFFFFFFu, idx, k + 0 + pair);
            int s1 = __shfl_sync(0xFFFFFFFFu, idx, k + 2 + pair);
            int s2 = __shfl_sync(0xFFFFFFFFu, idx, k + 4 + pair);
            int s3 = __shfl_sync(0xFFFFFFFFu, idx, k + 6 + pair);
            int s4 = __shfl_sync(0xFFFFFFFFu, idx, k + 8 + pair);
            int s5 = __shfl_sync(0xFFFFFFFFu, idx, k + 10 + pair);
            int s6 = __shfl_sync(0xFFFFFFFFu, idx, k + 12 + pair);
            int s7 = __shfl_sync(0xFFFFFFFFu, idx, k + 14 + pair);
            float4 v0 = H4[(size_t)s0 * (HID / 4) + q];
            float4 v1 = H4[(size_t)s1 * (HID / 4) + q];
            float4 v2 = H4[(size_t)s2 * (HID / 4) + q];
            float4 v3 = H4[(size_t)s3 * (HID / 4) + q];
            float4 v4 = H4[(size_t)s4 * (HID / 4) + q];
            float4 v5 = H4[(size_t)s5 * (HID / 4) + q];
            float4 v6 = H4[(size_t)s6 * (HID / 4) + q];
            float4 v7 = H4[(size_t)s7 * (HID / 4) + q];
            acc.x += ((v0.x + v1.x) + (v2.x + v3.x)) + ((v4.x + v5.x) + (v6.x + v7.x));
            acc.y += ((v0.y + v1.y) + (v2.y + v3.y)) + ((v4.y + v5.y) + (v6.y + v7.y));
            acc.z += ((v0.z + v1.z) + (v2.z + v3.z)) + ((v4.z + v5.z) + (v6.z + v7.z));
            acc.w += ((v0.w + v1.w) + (v2.w + v3.w)) + ((v4.w + v5.w) + (v6.w + v7.w));
        }
        for (; k + 2 <= m; k += 2) {
            int s = __shfl_sync(0xFFFFFFFFu, idx, k + pair);
            float4 v = H4[(size_t)s * (HID / 4) + q];
            acc.x += v.x; acc.y += v.y; acc.z += v.z; acc.w += v.w;
        }
        if (k < m) {  // odd remainder: only half-warp 0 accumulates it
            int s = __shfl_sync(0xFFFFFFFFu, idx, m - 1);
            if (pair == 0) {
                float4 v = H4[(size_t)s * (HID / 4) + q];
                acc.x += v.x; acc.y += v.y; acc.z += v.z; acc.w += v.w;
            }
        }
    }

    // combine the two half-warp partials (lanes L and L^16 hold same channels)
    acc.x += __shfl_xor_sync(0xFFFFFFFFu, acc.x, 16);
    acc.y += __shfl_xor_sync(0xFFFFFFFFu, acc.y, 16);
    acc.z += __shfl_xor_sync(0xFFFFFFFFu, acc.z, 16);
    acc.w += __shfl_xor_sync(0xFFFFFFFFu, acc.w, 16);

    if (pair == 0) {
        float4 self = H4[(size_t)dst * (HID / 4) + q];  // row carries own dinv
        float di = rsqrtf((float)(cnt + 1));
        float4 b = ((const float4*)bias)[q];
        float4 v;
        v.x = (acc.x + self.x) * di + b.x;
        v.y = (acc.y + self.y) * di + b.y;
        v.z = (acc.z + self.z) * di + b.z;
        v.w = (acc.w + self.w) * di + b.w;
        if (RELU) {
            v.x = fmaxf(v.x, 0.f);
            v.y = fmaxf(v.y, 0.f);
            v.z = fmaxf(v.z, 0.f);
            v.w = fmaxf(v.w, 0.f);
        }
        ((float4*)O)[(size_t)dst * (HID / 4) + q] = v;
    }
}

// ---------------- launch ----------------
extern "C" void kernel_launch(void* const* d_in, const int* in_sizes, int n_in,
                              void* d_out, int out_size) {
    const float* x = (const float*)d_in[0];
    const void* ei = d_in[1];
    const float* W1 = (const float*)d_in[2];
    const float* b1 = (const float*)d_in[3];
    const float* W2 = (const float*)d_in[4];
    const float* b2 = (const float*)d_in[5];
    float* out = (float*)d_out;

    int N = in_sizes[0] / CIN;
    int E = in_sizes[1] / 2;

    int nbN = (N + 255) / 256;
    int nbE = (E + 255) / 256;
    int nbG = (N + 127) / 128;
    int nbA = (N * 32 + 255) / 256;

    // 0: zero degree counters + dtype detect
    k_setup<<<nbN, 256>>>((const unsigned int*)ei, N);
    // 1: ELL build; slot counter doubles as degree histogram
    k_build<<<nbE, 256>>>(ei, E, N);
    // 2: gemm1 (dinv-scaled via g_cnt)
    k_gemm1<<<nbG, 128>>>(x, W1, g_h, N);
    // 3: layer-1 aggregate (+relu +bias)   <- ncu capture lands here
    k_agg<true><<<nbA, 256>>>(g_h, b1, g_a, N);
    // 4: gemm2 (dinv-scaled)
    k_gemm2<<<nbG, 128>>>(g_a, W2, g_h, N);
    // 5: layer-2 aggregate (+bias) -> d_out
    k_agg<false><<<nbA, 256>>>(g_h, b2, out, N);
}

// round 17
// speedup vs baseline: 18.3235x; 18.3235x over previous
#include <cuda_runtime.h>
#include <cuda_fp16.h>

#define NMAX 100000
#define EMAX 3200000
#define CIN 128
#define HID 64
#define CAP 128   // max tracked degree (Poisson(32): max observed deg ~ 70)

// ---------------- device scratch (no allocations allowed) ----------------
__device__ int   g_cnt[NMAX];     // build slot counter == degree histogram
__device__ int   g_is64;
__device__ int   g_ell[(size_t)NMAX * CAP];
__device__ uint4 g_hh4[(size_t)NMAX * HID / 8];  // fp16 message rows, 16B-aligned
__device__ float g_a[(size_t)NMAX * HID];        // fp32 layer-1 activations

__device__ __forceinline__ int load_idx(const void* ei, size_t pos, int is64) {
    return is64 ? (int)((const long long*)ei)[pos] : ((const int*)ei)[pos];
}

// ---------------- launch 0: zero counters + parallel dtype detect ----------
__global__ void k_setup(const unsigned int* __restrict__ ew, int N) {
    int i = blockIdx.x * blockDim.x + threadIdx.x;
    if (i < N) g_cnt[i] = 0;
    if (blockIdx.x == 0) {
        __shared__ int bad;
        if (threadIdx.x == 0) bad = 0;
        __syncthreads();
        // int64 edge values < 2^32 have zero high 32-bit words; int32 data won't.
        if (threadIdx.x < 64 && ew[2 * threadIdx.x + 1] != 0u) atomicExch(&bad, 1);
        __syncthreads();
        if (threadIdx.x == 0) g_is64 = bad ? 0 : 1;
    }
}

// ---------------- launch 1: ELL adjacency build (slot counter == degree) ----
__global__ void k_build(const void* __restrict__ ei, int E, int N) {
    int e = blockIdx.x * blockDim.x + threadIdx.x;
    if (e < E) {
        int is64 = g_is64;
        int d = load_idx(ei, (size_t)E + e, is64);
        if ((unsigned)d < (unsigned)N) {
            int s = load_idx(ei, e, is64);
            if ((unsigned)s >= (unsigned)N) s = d;
            int p = atomicAdd(&g_cnt[d], 1);
            if (p < CAP) g_ell[(size_t)d * CAP + p] = s;
        }
    }
}

// ---- GEMM body: Hh[row,:] = half( (X[row,:] @ W) * rsqrt(cnt[row]+1) ) ------
template <int CINT, int COUT>
__device__ __forceinline__ void gemm_rows(const float* __restrict__ X,
                                          const float* __restrict__ W,
                                          int N, int rowBlock) {
    __shared__ float4 sW[CINT * COUT / 4];
    for (int i = threadIdx.x; i < CINT * COUT / 4; i += blockDim.x)
        sW[i] = ((const float4*)W)[i];
    __syncthreads();

    int row = rowBlock * blockDim.x + threadIdx.x;
    if (row >= N) return;

    float acc[COUT];
#pragma unroll
    for (int j = 0; j < COUT; j++) acc[j] = 0.f;

    const float4* x4 = (const float4*)(X + (size_t)row * CINT);
#pragma unroll 2
    for (int k4 = 0; k4 < CINT / 4; k4++) {
        float4 xv = x4[k4];
        int k = k4 * 4;
#pragma unroll
        for (int kk = 0; kk < 4; kk++) {
            float xs = (kk == 0) ? xv.x : (kk == 1) ? xv.y : (kk == 2) ? xv.z : xv.w;
            const float4* wr = &sW[(k + kk) * (COUT / 4)];
#pragma unroll
            for (int j4 = 0; j4 < COUT / 4; j4++) {
                float4 w = wr[j4];
                acc[4 * j4 + 0] += xs * w.x;
                acc[4 * j4 + 1] += xs * w.y;
                acc[4 * j4 + 2] += xs * w.z;
                acc[4 * j4 + 3] += xs * w.w;
            }
        }
    }
    float sc = rsqrtf((float)(g_cnt[row] + 1));  // dinv folding (+1 self loop)

    __half2 hp[COUT / 2];
#pragma unroll
    for (int j = 0; j < COUT / 2; j++)
        hp[j] = __floats2half2_rn(acc[2 * j] * sc, acc[2 * j + 1] * sc);
    uint4* dst = &g_hh4[(size_t)row * (COUT / 8)];
#pragma unroll
    for (int i = 0; i < COUT / 8; i++) dst[i] = ((const uint4*)hp)[i];
}

__global__ void __launch_bounds__(128) k_gemm1(const float* __restrict__ X,
                                               const float* __restrict__ W1, int N) {
    gemm_rows<CIN, HID>(X, W1, N, blockIdx.x);
}

__global__ void __launch_bounds__(128) k_gemm2(const float* __restrict__ A,
                                               const float* __restrict__ W2, int N) {
    gemm_rows<HID, HID>(A, W2, N, blockIdx.x);
}

// ---------------- launches 3/5: ELL gather-aggregate over fp16 rows ----------
// One warp per dst; lane = half2 channel pair. One 128B line per edge.
// Coalesced 32-id index loads, shfl broadcast, 8 gathers in flight; fp32 acc.
template <bool RELU>
__global__ void __launch_bounds__(256) k_agg(const float* __restrict__ bias,
                                             float* __restrict__ O, int N) {
    int warp = (blockIdx.x * blockDim.x + threadIdx.x) >> 5;
    int lane = threadIdx.x & 31;
    if (warp >= N) return;
    int dst = warp;

    int cnt = g_cnt[dst];
    int deg = cnt < CAP ? cnt : CAP;
    const int* __restrict__ ell = g_ell + (size_t)dst * CAP;
    const __half2* __restrict__ H2 = (const __half2*)g_hh4;

    float ax = 0.f, ay = 0.f;

    for (int j0 = 0; j0 < deg; j0 += 32) {
        int m = deg - j0;
        if (m > 32) m = 32;
        int idx = (lane < m) ? ell[j0 + lane] : 0;  // one coalesced LDG: 32 ids

        int k = 0;
        for (; k + 8 <= m; k += 8) {
            int s0 = __shfl_sync(0xFFFFFFFFu, idx, k + 0);
            int s1 = __shfl_sync(0xFFFFFFFFu, idx, k + 1);
            int s2 = __shfl_sync(0xFFFFFFFFu, idx, k + 2);
            int s3 = __shfl_sync(0xFFFFFFFFu, idx, k + 3);
            int s4 = __shfl_sync(0xFFFFFFFFu, idx, k + 4);
            int s5 = __shfl_sync(0xFFFFFFFFu, idx, k + 5);
            int s6 = __shfl_sync(0xFFFFFFFFu, idx, k + 6);
            int s7 = __shfl_sync(0xFFFFFFFFu, idx, k + 7);
            __half2 h0 = H2[(size_t)s0 * 32 + lane];
            __half2 h1 = H2[(size_t)s1 * 32 + lane];
            __half2 h2 = H2[(size_t)s2 * 32 + lane];
            __half2 h3 = H2[(size_t)s3 * 32 + lane];
            __half2 h4 = H2[(size_t)s4 * 32 + lane];
            __half2 h5 = H2[(size_t)s5 * 32 + lane];
            __half2 h6 = H2[(size_t)s6 * 32 + lane];
            __half2 h7 = H2[(size_t)s7 * 32 + lane];
            float2 f0 = __half22float2(h0);
            float2 f1 = __half22float2(h1);
            float2 f2 = __half22float2(h2);
            float2 f3 = __half22float2(h3);
            float2 f4 = __half22float2(h4);
            float2 f5 = __half22float2(h5);
            float2 f6 = __half22float2(h6);
            float2 f7 = __half22float2(h7);
            ax += ((f0.x + f1.x) + (f2.x + f3.x)) + ((f4.x + f5.x) + (f6.x + f7.x));
            ay += ((f0.y + f1.y) + (f2.y + f3.y)) + ((f4.y + f5.y) + (f6.y + f7.y));
        }
        for (; k < m; k++) {
            int s = __shfl_sync(0xFFFFFFFFu, idx, k);
            float2 f = __half22float2(H2[(size_t)s * 32 + lane]);
            ax += f.x;
            ay += f.y;
        }
    }

    // self loop: row already carries its own dinv factor
    float2 fd = __half22float2(H2[(size_t)dst * 32 + lane]);
    ax += fd.x;
    ay += fd.y;

    float di = rsqrtf((float)(cnt + 1));
    float2 b = ((const float2*)bias)[lane];
    float ox = ax * di + b.x;
    float oy = ay * di + b.y;
    if (RELU) {
        ox = fmaxf(ox, 0.f);
        oy = fmaxf(oy, 0.f);
    }
    ((float2*)O)[(size_t)dst * 32 + lane] = make_float2(ox, oy);
}

// ---------------- launch ----------------
extern "C" void kernel_launch(void* const* d_in, const int* in_sizes, int n_in,
                              void* d_out, int out_size) {
    const float* x = (const float*)d_in[0];
    const void* ei = d_in[1];
    const float* W1 = (const float*)d_in[2];
    const float* b1 = (const float*)d_in[3];
    const float* W2 = (const float*)d_in[4];
    const float* b2 = (const float*)d_in[5];
    float* out = (float*)d_out;

    int N = in_sizes[0] / CIN;
    int E = in_sizes[1] / 2;

    int nbN = (N + 255) / 256;
    int nbE = (E + 255) / 256;
    int nbG = (N + 127) / 128;
    int nbA = (N * 32 + 255) / 256;

    // 0: zero degree counters + dtype detect
    k_setup<<<nbN, 256>>>((const unsigned int*)ei, N);
    // 1: ELL build; slot counter doubles as degree histogram
    k_build<<<nbE, 256>>>(ei, E, N);
    // 2: gemm1 -> fp16 message rows (dinv-scaled)
    k_gemm1<<<nbG, 128>>>(x, W1, N);
    // 3: layer-1 aggregate (+relu +bias) -> fp32 a   <- ncu capture lands here
    k_agg<true><<<nbA, 256>>>(b1, g_a, N);
    // 4: gemm2 -> fp16 message rows (dinv-scaled)
    k_gemm2<<<nbG, 128>>>(g_a, W2, N);
    // 5: layer-2 aggregate (+bias) -> d_out (fp32)
    k_agg<false><<<nbA, 256>>>(b2, out, N);
}